// round 14
// baseline (speedup 1.0000x reference)
#include <cuda_runtime.h>
#include <cstdint>

#define BB 16384
#define KK 64
#define NA 16

#define GF_BYTES 18432u          // 128 blocks * 36 floats * 4
#define R_BYTES  9216u           // 64 blocks * 36 floats * 4
#define NPROD 64                 // producer CTAs
#define NFLAG 64                 // flag lines (128B apart)

// Rotation table: R[action][k][6][6] (144 KB), 128B-aligned.
__device__ __align__(128) float d_R[NA * KK * 36];
__device__ unsigned g_done = 0;                 // producer completion counter
__device__ unsigned g_fin  = 0;                 // retirement counter
__device__ __align__(128) unsigned g_flag[NFLAG * 32];  // 1 flag per 128B line

static __device__ __forceinline__ uint32_t smem_u32(const void* p) {
    uint32_t a;
    asm("{ .reg .u64 t; cvta.to.shared.u64 t, %1; cvt.u32.u64 %0, t; }"
        : "=r"(a) : "l"(p));
    return a;
}

static __device__ __forceinline__ void mbar_wait0(uint32_t bar_a) {
    uint32_t done;
    asm volatile(
        "{\n\t.reg .pred p;\n\t"
        "mbarrier.try_wait.parity.acquire.cta.shared::cta.b64 p, [%1], 0;\n\t"
        "selp.b32 %0, 1, 0, p;\n\t}"
        : "=r"(done) : "r"(bar_a) : "memory");
    if (!done) {
        asm volatile(
            "{\n\t.reg .pred P1;\n\t"
            "WL_%=:\n\t"
            "mbarrier.try_wait.parity.acquire.cta.shared::cta.b64 P1, [%0], 0, 0x989680;\n\t"
            "@P1 bra.uni WD_%=;\n\t"
            "bra.uni WL_%=;\n\t"
            "WD_%=:\n\t}"
            :: "r"(bar_a) : "memory");
    }
}

// ---------------------------------------------------------------------------
// Single fused kernel, grid 8192 x 128 (6 CTAs/SM), R5's proven datapath.
//  - All CTAs: issue gf TMA immediately (overlaps everything).
//  - CTAs 0..63: column-parallel expm (16 matrices x 6 cols on threads 0..95)
//    into d_R; last producer releases 64 spread flag lines.
//  - t0: poll flag[bid&63], then TMA the CTA's two R slices; compute; bulk
//    store out. Last retiring CTA resets flags for graph replay.
// ---------------------------------------------------------------------------
__global__ void __launch_bounds__(128, 6) fused_kernel(
    const float* __restrict__ gf,
    const int* __restrict__ act,
    const float* __restrict__ act_params,
    const float* __restrict__ basis,
    float* __restrict__ out) {
    __shared__ __align__(128) float sG[128 * 36];   // 18 KB, reused for output
    __shared__ __align__(128) float sR[128 * 36];   // 18 KB (scratch pre-R-load)
    __shared__ __align__(8) unsigned long long mbar[2];

    const int t = threadIdx.x;
    const unsigned bid = blockIdx.x;
    const uint32_t sG_a = smem_u32(sG);
    const uint32_t sR_a = smem_u32(sR);
    const uint32_t bar0 = smem_u32(&mbar[0]);
    const uint32_t bar1 = smem_u32(&mbar[1]);

    if (t == 0) {
        asm volatile("mbarrier.init.shared.b64 [%0], 1;" :: "r"(bar0) : "memory");
        asm volatile("mbarrier.init.shared.b64 [%0], 1;" :: "r"(bar1) : "memory");
    }
    __syncthreads();

    // gf load: no dependency on R — issue immediately.
    if (t == 0) {
        asm volatile("mbarrier.arrive.expect_tx.shared.b64 _, [%0], %1;"
                     :: "r"(bar0), "r"(GF_BYTES) : "memory");
        const char* gsrc = reinterpret_cast<const char*>(gf) +
                           (size_t)bid * GF_BYTES;
        asm volatile(
            "cp.async.bulk.shared::cta.global.mbarrier::complete_tx::bytes "
            "[%0], [%1], %2, [%3];"
            :: "r"(sG_a), "l"(gsrc), "r"(GF_BYTES), "r"(bar0) : "memory");
    }

    // ---- Producer CTAs: column-parallel expm while gf streams chip-wide ----
    if (bid < NPROD) {
        const bool worker = (t < 96);
        int s = 0, lm = 0, c = 0, mat = 0;
        float v[6];
        float A[36];
        if (worker) {
            lm = t / 6;                          // local matrix 0..15
            c = t - lm * 6;                      // column 0..5
            mat = (int)bid * 16 + lm;            // 0..1023
            const int action = mat >> 6;
            const int k = mat & 63;

            float a = act_params[action * KK + k];
            const float* L = basis + k * 36;
#pragma unroll
            for (int i = 0; i < 6; i++)
#pragma unroll
                for (int j = 0; j < 6; j++)
                    A[i * 6 + j] = a * (L[i * 6 + j] - L[j * 6 + i]);

            float nrm = 0.f;
#pragma unroll
            for (int i = 0; i < 6; i++) {
                float rs = 0.f;
#pragma unroll
                for (int j = 0; j < 6; j++) rs += fabsf(A[i * 6 + j]);
                nrm = fmaxf(nrm, rs);
            }
            while (nrm > 0.5f && s < 40) { nrm *= 0.5f; s++; }
            float sc = ldexpf(1.0f, -s);
#pragma unroll
            for (int i = 0; i < 36; i++) A[i] *= sc;

            // Taylor order 10 on column c
#pragma unroll
            for (int i = 0; i < 6; i++) v[i] = (i == c) ? 1.f : 0.f;
#pragma unroll
            for (int p = 10; p >= 1; --p) {
                float w[6];
                float inv = 1.0f / (float)p;
#pragma unroll
                for (int i = 0; i < 6; i++) {
                    float acc = 0.f;
#pragma unroll
                    for (int j = 0; j < 6; j++)
                        acc = fmaf(A[i * 6 + j], v[j], acc);
                    w[i] = acc * inv + ((i == c) ? 1.f : 0.f);
                }
#pragma unroll
                for (int i = 0; i < 6; i++) v[i] = w[i];
            }
        }
        // Squaring (rare): scratch in sR (dead until the R TMA lands later).
        for (int q = 0; ; q++) {
            bool active = worker && (q < s);
            if (!__syncthreads_or(active)) break;
            if (active) {
#pragma unroll
                for (int i = 0; i < 6; i++) sR[lm * 36 + i * 6 + c] = v[i];
            }
            __syncthreads();
            if (active) {
                float w[6];
#pragma unroll
                for (int i = 0; i < 6; i++) {
                    float acc = 0.f;
#pragma unroll
                    for (int j = 0; j < 6; j++)
                        acc = fmaf(sR[lm * 36 + i * 6 + j], v[j], acc);
                    w[i] = acc;
                }
#pragma unroll
                for (int i = 0; i < 6; i++) v[i] = w[i];
            }
        }
        if (worker) {
#pragma unroll
            for (int i = 0; i < 6; i++)
                d_R[mat * 36 + i * 6 + c] = v[i];
        }
        __syncthreads();
        if (t == 0) {
            __threadfence();                                  // d_R -> L2
            asm volatile("fence.proxy.async;" ::: "memory");  // generic->async
            unsigned old;
            asm volatile("atom.acq_rel.gpu.global.add.u32 %0, [%1], 1;"
                         : "=r"(old) : "l"(&g_done) : "memory");
            if (old == NPROD - 1u) {
                // Last producer: release all flag lines.
#pragma unroll 4
                for (int f = 0; f < NFLAG; f++)
                    asm volatile("st.release.gpu.global.u32 [%0], 1;"
                                 :: "l"(&g_flag[f * 32]) : "memory");
            }
        }
    }

    // ---- t0: wait for table, then fetch this CTA's two R slices ----
    if (t == 0) {
        const unsigned b0 = bid * 2u;
        int a0 = __ldg(act + b0);
        int a1 = __ldg(act + b0 + 1);

        const unsigned* fl = &g_flag[(bid & (NFLAG - 1u)) * 32];
        unsigned fv;
        do {
            asm volatile("ld.acquire.gpu.global.u32 %0, [%1];"
                         : "=r"(fv) : "l"(fl) : "memory");
            if (fv) break;
            asm volatile("nanosleep.u32 64;");
        } while (true);
        asm volatile("fence.proxy.async;" ::: "memory");

        asm volatile("mbarrier.arrive.expect_tx.shared.b64 _, [%0], %1;"
                     :: "r"(bar1), "r"(2u * R_BYTES) : "memory");
        const char* rbase = reinterpret_cast<const char*>(d_R);
        asm volatile(
            "cp.async.bulk.shared::cta.global.mbarrier::complete_tx::bytes "
            "[%0], [%1], %2, [%3];"
            :: "r"(sR_a), "l"(rbase + (size_t)a0 * R_BYTES), "r"(R_BYTES),
               "r"(bar1) : "memory");
        asm volatile(
            "cp.async.bulk.shared::cta.global.mbarrier::complete_tx::bytes "
            "[%0], [%1], %2, [%3];"
            :: "r"(sR_a + R_BYTES), "l"(rbase + (size_t)a1 * R_BYTES),
               "r"(R_BYTES), "r"(bar1) : "memory");
    }

    mbar_wait0(bar0);   // gf ready
    mbar_wait0(bar1);   // R ready

    // ---- Compute: thread t owns block #t; conflict-free LDS.128 ----
    float4* sG4 = reinterpret_cast<float4*>(sG);
    float4* sR4 = reinterpret_cast<float4*>(sR);

    float G[36];
    const float4* myG = sG4 + t * 9;
#pragma unroll
    for (int q = 0; q < 9; q++) {
        float4 v = myG[q];
        G[4 * q + 0] = v.x; G[4 * q + 1] = v.y;
        G[4 * q + 2] = v.z; G[4 * q + 3] = v.w;
    }

    const float4* myR = sR4 + t * 9;
    float4* myO = sG4 + t * 9;                  // overwrite own G region
#pragma unroll
    for (int rp = 0; rp < 3; rp++) {
        float r[12];
#pragma unroll
        for (int q = 0; q < 3; q++) {
            float4 v = myR[rp * 3 + q];
            r[4 * q + 0] = v.x; r[4 * q + 1] = v.y;
            r[4 * q + 2] = v.z; r[4 * q + 3] = v.w;
        }
        float p[12];
#pragma unroll
        for (int l = 0; l < 6; l++) {
            float acc0 = 0.f, acc1 = 0.f;
#pragma unroll
            for (int j = 0; j < 6; j++) {
                acc0 = fmaf(r[j],     G[j * 6 + l], acc0);
                acc1 = fmaf(r[6 + j], G[j * 6 + l], acc1);
            }
            p[l] = acc0; p[6 + l] = acc1;
        }
#pragma unroll
        for (int q = 0; q < 3; q++) {
            float4 v;
            v.x = p[4 * q + 0]; v.y = p[4 * q + 1];
            v.z = p[4 * q + 2]; v.w = p[4 * q + 3];
            myO[rp * 3 + q] = v;
        }
    }

    asm volatile("fence.proxy.async.shared::cta;" ::: "memory");
    __syncthreads();

    if (t == 0) {
        char* gdst = reinterpret_cast<char*>(out) + (size_t)bid * GF_BYTES;
        asm volatile(
            "cp.async.bulk.global.shared::cta.bulk_group [%0], [%1], %2;"
            :: "l"(gdst), "r"(sG_a), "r"(GF_BYTES) : "memory");
        asm volatile("cp.async.bulk.commit_group;" ::: "memory");
        asm volatile("cp.async.bulk.wait_group 0;" ::: "memory");

        // Retirement; last CTA resets replay state. Every CTA has already
        // passed its poll before g_fin can reach 8191.
        unsigned old = atomicAdd(&g_fin, 1u);
        if (old == (BB / 2) - 1u) {
            atomicExch(&g_done, 0u);
#pragma unroll 4
            for (int f = 0; f < NFLAG; f++)
                atomicExch(&g_flag[f * 32], 0u);
            atomicExch(&g_fin, 0u);
        }
    }
}

// ---------------------------------------------------------------------------
// Inputs (metadata order): group_feats f32 [B,K*36], act i32 [B],
// act_params f32 [16,K], lie_alg_basis f32 [K,6,6]. Output f32 [B,K*36].
// ---------------------------------------------------------------------------
extern "C" void kernel_launch(void* const* d_in, const int* in_sizes, int n_in,
                              void* d_out, int out_size) {
    const float* gf         = (const float*)d_in[0];
    const int*   act        = (const int*)d_in[1];
    const float* act_params = (const float*)d_in[2];
    const float* basis      = (const float*)d_in[3];
    float* out = (float*)d_out;

    fused_kernel<<<BB / 2, 128>>>(gf, act, act_params, basis, out);
}

// round 15
// speedup vs baseline: 1.5594x; 1.5594x over previous
#include <cuda_runtime.h>
#include <cstdint>

#define BB 16384
#define KK 64
#define NA 16

#define BLK_BYTES 9216u          // 64 blocks * 36 floats * 4 (one b-value)

// Precomputed rotation table: R[action][k][6][6]  (144 KB), 128B-aligned.
__device__ __align__(128) float d_R[NA * KK * 36];

static __device__ __forceinline__ uint32_t smem_u32(const void* p) {
    uint32_t a;
    asm("{ .reg .u64 t; cvta.to.shared.u64 t, %1; cvt.u32.u64 %0, t; }"
        : "=r"(a) : "l"(p));
    return a;
}

static __device__ __forceinline__ void mbar_wait0(uint32_t bar_a) {
    uint32_t done;
    asm volatile(
        "{\n\t.reg .pred p;\n\t"
        "mbarrier.try_wait.parity.acquire.cta.shared::cta.b64 p, [%1], 0;\n\t"
        "selp.b32 %0, 1, 0, p;\n\t}"
        : "=r"(done) : "r"(bar_a) : "memory");
    if (!done) {
        asm volatile(
            "{\n\t.reg .pred P1;\n\t"
            "WL_%=:\n\t"
            "mbarrier.try_wait.parity.acquire.cta.shared::cta.b64 P1, [%0], 0, 0x989680;\n\t"
            "@P1 bra.uni WD_%=;\n\t"
            "bra.uni WL_%=;\n\t"
            "WD_%=:\n\t}"
            :: "r"(bar_a) : "memory");
    }
}

// ---------------------------------------------------------------------------
// Kernel 1: column-parallel expm (R11's proven version). 32 CTAs x 192 thr.
// Thread = (matrix, column); releases the dependent grid when table written.
// ---------------------------------------------------------------------------
__global__ void __launch_bounds__(192, 1) expm_kernel(
    const float* __restrict__ act_params,
    const float* __restrict__ basis) {
    __shared__ float sT[32 * 36];

    const int t = threadIdx.x;               // 0..191
    const int lm = t / 6;                    // local matrix 0..31
    const int c = t - lm * 6;                // column 0..5
    const int mat = blockIdx.x * 32 + lm;    // 0..1023
    const int action = mat >> 6;
    const int k = mat & 63;

    float a = act_params[action * KK + k];
    const float* L = basis + k * 36;

    float A[36];
#pragma unroll
    for (int i = 0; i < 6; i++)
#pragma unroll
        for (int j = 0; j < 6; j++)
            A[i * 6 + j] = a * (L[i * 6 + j] - L[j * 6 + i]);

    float nrm = 0.f;
#pragma unroll
    for (int i = 0; i < 6; i++) {
        float rs = 0.f;
#pragma unroll
        for (int j = 0; j < 6; j++) rs += fabsf(A[i * 6 + j]);
        nrm = fmaxf(nrm, rs);
    }

    int s = 0;
    while (nrm > 0.5f && s < 40) { nrm *= 0.5f; s++; }
    float sc = ldexpf(1.0f, -s);
#pragma unroll
    for (int i = 0; i < 36; i++) A[i] *= sc;

    float v[6];
#pragma unroll
    for (int i = 0; i < 6; i++) v[i] = (i == c) ? 1.f : 0.f;

#pragma unroll
    for (int p = 10; p >= 1; --p) {
        float w[6];
        float inv = 1.0f / (float)p;
#pragma unroll
        for (int i = 0; i < 6; i++) {
            float acc = 0.f;
#pragma unroll
            for (int j = 0; j < 6; j++)
                acc = fmaf(A[i * 6 + j], v[j], acc);
            w[i] = acc * inv + ((i == c) ? 1.f : 0.f);
        }
#pragma unroll
        for (int i = 0; i < 6; i++) v[i] = w[i];
    }

    // Squaring (rare) via per-matrix smem T; uniform loop.
    for (int q = 0; ; q++) {
        bool active = (q < s);
        if (!__syncthreads_or(active)) break;
        if (active) {
#pragma unroll
            for (int i = 0; i < 6; i++) sT[lm * 36 + i * 6 + c] = v[i];
        }
        __syncthreads();
        if (active) {
            float w[6];
#pragma unroll
            for (int i = 0; i < 6; i++) {
                float acc = 0.f;
#pragma unroll
                for (int j = 0; j < 6; j++)
                    acc = fmaf(sT[lm * 36 + i * 6 + j], v[j], acc);
                w[i] = acc;
            }
#pragma unroll
            for (int i = 0; i < 6; i++) v[i] = w[i];
        }
    }

#pragma unroll
    for (int i = 0; i < 6; i++)
        d_R[mat * 36 + i * 6 + c] = v[i];

    __threadfence();
    asm volatile("griddepcontrol.launch_dependents;" ::: "memory");
}

// ---------------------------------------------------------------------------
// Kernel 2: apply, 64-thread CTAs (1 b-value each), 12 CTAs/SM.
// Same per-thread datapath as the 45us kernel; twice the independent
// load->compute->store pipelines per SM.
// ---------------------------------------------------------------------------
__global__ void __launch_bounds__(64, 12) apply_kernel(
    const float* __restrict__ gf,
    const int* __restrict__ act,
    float* __restrict__ out) {
    __shared__ __align__(128) float sG[64 * 36];    // 9 KB, reused for output
    __shared__ __align__(128) float sR[64 * 36];    // 9 KB
    __shared__ __align__(8) unsigned long long mbar[2];

    const int t = threadIdx.x;                       // 0..63
    const unsigned bid = blockIdx.x;                 // 0..16383 (= b)
    const uint32_t sG_a = smem_u32(sG);
    const uint32_t sR_a = smem_u32(sR);
    const uint32_t bar0 = smem_u32(&mbar[0]);
    const uint32_t bar1 = smem_u32(&mbar[1]);

    if (t == 0) {
        asm volatile("mbarrier.init.shared.b64 [%0], 1;" :: "r"(bar0) : "memory");
        asm volatile("mbarrier.init.shared.b64 [%0], 1;" :: "r"(bar1) : "memory");
    }
    __syncthreads();

    if (t == 0) {
        // gf load: no dependency on the expm table — issue immediately.
        asm volatile("mbarrier.arrive.expect_tx.shared.b64 _, [%0], %1;"
                     :: "r"(bar0), "r"(BLK_BYTES) : "memory");
        const char* gsrc = reinterpret_cast<const char*>(gf) +
                           (size_t)bid * BLK_BYTES;
        asm volatile(
            "cp.async.bulk.shared::cta.global.mbarrier::complete_tx::bytes "
            "[%0], [%1], %2, [%3];"
            :: "r"(sG_a), "l"(gsrc), "r"(BLK_BYTES), "r"(bar0) : "memory");

        int a0 = __ldg(act + bid);

        // Block until the expm kernel has released its results.
        asm volatile("griddepcontrol.wait;" ::: "memory");

        asm volatile("mbarrier.arrive.expect_tx.shared.b64 _, [%0], %1;"
                     :: "r"(bar1), "r"(BLK_BYTES) : "memory");
        const char* rbase = reinterpret_cast<const char*>(d_R);
        asm volatile(
            "cp.async.bulk.shared::cta.global.mbarrier::complete_tx::bytes "
            "[%0], [%1], %2, [%3];"
            :: "r"(sR_a), "l"(rbase + (size_t)a0 * BLK_BYTES), "r"(BLK_BYTES),
               "r"(bar1) : "memory");
    }

    mbar_wait0(bar0);   // gf ready
    mbar_wait0(bar1);   // R ready

    // Compute: thread t owns k-block #t. Conflict-free LDS.128, 144B stride.
    float4* sG4 = reinterpret_cast<float4*>(sG);
    float4* sR4 = reinterpret_cast<float4*>(sR);

    float G[36];
    const float4* myG = sG4 + t * 9;
#pragma unroll
    for (int q = 0; q < 9; q++) {
        float4 v = myG[q];
        G[4 * q + 0] = v.x; G[4 * q + 1] = v.y;
        G[4 * q + 2] = v.z; G[4 * q + 3] = v.w;
    }

    const float4* myR = sR4 + t * 9;
    float4* myO = sG4 + t * 9;                  // overwrite own G region
#pragma unroll
    for (int rp = 0; rp < 3; rp++) {
        float r[12];
#pragma unroll
        for (int q = 0; q < 3; q++) {
            float4 v = myR[rp * 3 + q];
            r[4 * q + 0] = v.x; r[4 * q + 1] = v.y;
            r[4 * q + 2] = v.z; r[4 * q + 3] = v.w;
        }
        float p[12];
#pragma unroll
        for (int l = 0; l < 6; l++) {
            float acc0 = 0.f, acc1 = 0.f;
#pragma unroll
            for (int j = 0; j < 6; j++) {
                acc0 = fmaf(r[j],     G[j * 6 + l], acc0);
                acc1 = fmaf(r[6 + j], G[j * 6 + l], acc1);
            }
            p[l] = acc0; p[6 + l] = acc1;
        }
#pragma unroll
        for (int q = 0; q < 3; q++) {
            float4 v;
            v.x = p[4 * q + 0]; v.y = p[4 * q + 1];
            v.z = p[4 * q + 2]; v.w = p[4 * q + 3];
            myO[rp * 3 + q] = v;
        }
    }

    asm volatile("fence.proxy.async.shared::cta;" ::: "memory");
    __syncthreads();

    if (t == 0) {
        char* gdst = reinterpret_cast<char*>(out) + (size_t)bid * BLK_BYTES;
        asm volatile(
            "cp.async.bulk.global.shared::cta.bulk_group [%0], [%1], %2;"
            :: "l"(gdst), "r"(sG_a), "r"(BLK_BYTES) : "memory");
        asm volatile("cp.async.bulk.commit_group;" ::: "memory");
        asm volatile("cp.async.bulk.wait_group 0;" ::: "memory");
    }
}

// ---------------------------------------------------------------------------
// Inputs (metadata order): group_feats f32 [B,K*36], act i32 [B],
// act_params f32 [16,K], lie_alg_basis f32 [K,6,6]. Output f32 [B,K*36].
// ---------------------------------------------------------------------------
extern "C" void kernel_launch(void* const* d_in, const int* in_sizes, int n_in,
                              void* d_out, int out_size) {
    const float* gf         = (const float*)d_in[0];
    const int*   act        = (const int*)d_in[1];
    const float* act_params = (const float*)d_in[2];
    const float* basis      = (const float*)d_in[3];
    float* out = (float*)d_out;

    expm_kernel<<<32, 192>>>(act_params, basis);

    // Secondary with programmatic dependent launch: prologue overlaps expm.
    cudaLaunchConfig_t cfg = {};
    cfg.gridDim = dim3(BB);
    cfg.blockDim = dim3(64);
    cfg.dynamicSmemBytes = 0;
    cfg.stream = 0;
    cudaLaunchAttribute attrs[1];
    attrs[0].id = cudaLaunchAttributeProgrammaticStreamSerialization;
    attrs[0].val.programmaticStreamSerializationAllowed = 1;
    cfg.attrs = attrs;
    cfg.numAttrs = 1;
    cudaLaunchKernelEx(&cfg, apply_kernel, gf, act, out);
}